// round 1
// baseline (speedup 1.0000x reference)
#include <cuda_runtime.h>
#include <cstdint>

#define N_NODES 100000
#define E_EDGES 1600000
#define E2 (E_EDGES + N_NODES)   // 1,700,000 with self loops
#define HID 64
#define IN_DIM 128
#define NEG_SLOPE 0.2f

// ---------------- scratch (device globals; no allocation allowed) -------------
__device__ float    g_h[(size_t)N_NODES * HID];     // transformed features (current layer)
__device__ float    g_acc[(size_t)N_NODES * HID];   // softmax-weighted aggregate
__device__ float    g_e[E2];                        // per-edge leaky-relu logits
__device__ float    g_as[N_NODES], g_ad[N_NODES];   // per-node alpha_src / alpha_dst
__device__ unsigned g_m[N_NODES];                   // segment max (order-encoded float)
__device__ float    g_denom[N_NODES];               // segment sum of exp
__device__ int      g_src[E2], g_dst[E2];           // converted int32 edge list (+loops)
__device__ int      g_is64;                         // edge_index dtype flag

// ---------------- helpers -----------------------------------------------------
__device__ __forceinline__ unsigned fenc(float f) {
    unsigned u = __float_as_uint(f);
    return (u & 0x80000000u) ? ~u : (u | 0x80000000u);
}
__device__ __forceinline__ float fdec(unsigned k) {
    unsigned u = (k & 0x80000000u) ? (k & 0x7fffffffu) : ~k;
    return __uint_as_float(u);
}
__device__ __forceinline__ float elu_f(float v) {
    return v > 0.f ? v : expm1f(v);
}

// ---------------- dtype probe: int64 edge_index reads as (val,0) int32 pairs --
__global__ void k_probe(const int* ei32) {
    __shared__ int nz;
    if (threadIdx.x == 0) nz = 0;
    __syncthreads();
    int any = 0;
    for (int i = threadIdx.x; i < 2048; i += 256)
        any |= (ei32[2 * i + 1] != 0);
    if (any) atomicOr(&nz, 1);
    __syncthreads();
    if (threadIdx.x == 0) g_is64 = (nz == 0) ? 1 : 0;
}

// ---------------- convert edge list to int32 + append self loops --------------
__global__ void k_convert(const void* ei) {
    int i = blockIdx.x * blockDim.x + threadIdx.x;
    if (i >= E2) return;
    int s, d;
    if (i < E_EDGES) {
        if (g_is64) {
            const long long* p = (const long long*)ei;
            s = (int)p[i]; d = (int)p[E_EDGES + i];
        } else {
            const int* p = (const int*)ei;
            s = p[i]; d = p[E_EDGES + i];
        }
    } else {
        s = d = i - E_EDGES;
    }
    g_src[i] = s;
    g_dst[i] = d;
}

// ---------------- layer1: h = x @ W1, alphas, init accumulators ---------------
// block = 256 threads handles 32 nodes.  3125 blocks (exact).
__global__ __launch_bounds__(256) void k_l1(const float* __restrict__ x,
                                            const float* __restrict__ W1,
                                            const float* __restrict__ as1,
                                            const float* __restrict__ ad1) {
    __shared__ float sW[IN_DIM * HID];   // 32 KB
    __shared__ float sx[32 * IN_DIM];    // 16 KB (reused as sh[32*65])
    int tid = threadIdx.x;
    int node0 = blockIdx.x * 32;

    {   // cooperative loads
        float4* dw = (float4*)sW; const float4* swg = (const float4*)W1;
        for (int i = tid; i < (IN_DIM * HID) / 4; i += 256) dw[i] = swg[i];
        float4* dx = (float4*)sx;
        const float4* sxg = (const float4*)(x + (size_t)node0 * IN_DIM);
        for (int i = tid; i < (32 * IN_DIM) / 4; i += 256) dx[i] = sxg[i];
    }
    __syncthreads();

    int d = tid & 63, g = tid >> 6;   // dim, node-group (8 nodes each)
    float acc[8];
#pragma unroll
    for (int j = 0; j < 8; j++) acc[j] = 0.f;

    for (int k = 0; k < IN_DIM; k += 4) {
        float w0 = sW[(k + 0) * HID + d];
        float w1 = sW[(k + 1) * HID + d];
        float w2 = sW[(k + 2) * HID + d];
        float w3 = sW[(k + 3) * HID + d];
#pragma unroll
        for (int j = 0; j < 8; j++) {
            float4 xv = *(const float4*)&sx[(g * 8 + j) * IN_DIM + k];
            acc[j] = fmaf(w0, xv.x, acc[j]);
            acc[j] = fmaf(w1, xv.y, acc[j]);
            acc[j] = fmaf(w2, xv.z, acc[j]);
            acc[j] = fmaf(w3, xv.w, acc[j]);
        }
    }
    __syncthreads();          // done with sx contents
    float* sh = sx;           // reuse as [32][65]
#pragma unroll
    for (int j = 0; j < 8; j++) {
        int n = g * 8 + j;
        int gn = node0 + n;
        sh[n * 65 + d] = acc[j];
        g_h[(size_t)gn * HID + d]   = acc[j];
        g_acc[(size_t)gn * HID + d] = 0.f;
    }
    __syncthreads();
    if (tid < 32) {
        int gn = node0 + tid;
        float s = 0.f, dd = 0.f;
#pragma unroll
        for (int k = 0; k < HID; k++) {
            float hv = sh[tid * 65 + k];
            s  = fmaf(hv, as1[k], s);
            dd = fmaf(hv, ad1[k], dd);
        }
        g_as[gn] = s; g_ad[gn] = dd;
        g_m[gn] = 0u; g_denom[gn] = 0.f;
    }
}

// ---------------- edge pass 1: logits + segment max ---------------------------
__global__ __launch_bounds__(256) void k_edge_max() {
    int i = blockIdx.x * blockDim.x + threadIdx.x;
    if (i >= E2) return;
    int s = g_src[i], d = g_dst[i];
    float e = g_as[s] + g_ad[d];
    e = fmaxf(e, NEG_SLOPE * e);   // leaky relu
    g_e[i] = e;
    atomicMax(&g_m[d], fenc(e));
}

// ---------------- edge pass 2: exp, denom, weighted scatter -------------------
// half-warp (16 lanes) per edge: float4 gather + red.global.add.v4.f32 scatter
__global__ __launch_bounds__(256) void k_edge_acc() {
    int t = blockIdx.x * 256 + threadIdx.x;
    int i = t >> 4;
    if (i >= E2) return;
    int r = threadIdx.x & 15;
    int s = g_src[i], d = g_dst[i];
    float e  = g_e[i];
    float mm = fdec(g_m[d]);
    float ex = __expf(e - mm);
    if (r == 0) atomicAdd(&g_denom[d], ex);
    const float4 hv = *(const float4*)&g_h[(size_t)s * HID + r * 4];
    float* ap = &g_acc[(size_t)d * HID + r * 4];
    asm volatile("red.global.add.v4.f32 [%0], {%1,%2,%3,%4};"
                 :: "l"(ap), "f"(ex * hv.x), "f"(ex * hv.y),
                    "f"(ex * hv.z), "f"(ex * hv.w)
                 : "memory");
}

// ---------------- finalize layer1 + layer2 GEMM + alphas + re-init ------------
__global__ __launch_bounds__(256) void k_l2(const float* __restrict__ W2,
                                            const float* __restrict__ as2,
                                            const float* __restrict__ ad2,
                                            const float* __restrict__ b1) {
    __shared__ float sW[HID * HID];   // 16 KB
    __shared__ float sh1[32 * 68];    // elu features (padded for float4)
    __shared__ float sh2[32 * 65];    // gemm output for alpha reduce
    int tid = threadIdx.x;
    int node0 = blockIdx.x * 32;
    {
        float4* dw = (float4*)sW; const float4* swg = (const float4*)W2;
        for (int i = tid; i < (HID * HID) / 4; i += 256) dw[i] = swg[i];
    }
    int d = tid & 63, g = tid >> 6;
#pragma unroll
    for (int j = 0; j < 8; j++) {
        int n = g * 8 + j;
        int gn = node0 + n;
        float v = g_acc[(size_t)gn * HID + d] / g_denom[gn] + b1[d];
        sh1[n * 68 + d] = elu_f(v);
    }
    __syncthreads();
    float acc[8];
#pragma unroll
    for (int j = 0; j < 8; j++) acc[j] = 0.f;
    for (int k = 0; k < HID; k += 4) {
        float w0 = sW[(k + 0) * HID + d];
        float w1 = sW[(k + 1) * HID + d];
        float w2 = sW[(k + 2) * HID + d];
        float w3 = sW[(k + 3) * HID + d];
#pragma unroll
        for (int j = 0; j < 8; j++) {
            float4 xv = *(const float4*)&sh1[(g * 8 + j) * 68 + k];
            acc[j] = fmaf(w0, xv.x, acc[j]);
            acc[j] = fmaf(w1, xv.y, acc[j]);
            acc[j] = fmaf(w2, xv.z, acc[j]);
            acc[j] = fmaf(w3, xv.w, acc[j]);
        }
    }
#pragma unroll
    for (int j = 0; j < 8; j++) {
        int n = g * 8 + j;
        int gn = node0 + n;
        sh2[n * 65 + d] = acc[j];
        g_h[(size_t)gn * HID + d]   = acc[j];
        g_acc[(size_t)gn * HID + d] = 0.f;
    }
    __syncthreads();
    if (tid < 32) {
        int gn = node0 + tid;
        float s = 0.f, dd = 0.f;
#pragma unroll
        for (int k = 0; k < HID; k++) {
            float hv = sh2[tid * 65 + k];
            s  = fmaf(hv, as2[k], s);
            dd = fmaf(hv, ad2[k], dd);
        }
        g_as[gn] = s; g_ad[gn] = dd;
        g_m[gn] = 0u; g_denom[gn] = 0.f;
    }
}

// ---------------- finalize layer2 + output head -------------------------------
// warp per node
__global__ __launch_bounds__(256) void k_out(const float* __restrict__ b2,
                                             const float* __restrict__ Wout,
                                             const float* __restrict__ bout,
                                             float* __restrict__ out) {
    int n = blockIdx.x * 8 + (threadIdx.x >> 5);
    if (n >= N_NODES) return;
    int lane = threadIdx.x & 31;
    float2 a = *(const float2*)&g_acc[(size_t)n * HID + lane * 2];
    float dnm = g_denom[n];
    float v0 = elu_f(a.x / dnm + b2[lane * 2]);
    float v1 = elu_f(a.y / dnm + b2[lane * 2 + 1]);
    float p = v0 * Wout[lane * 2] + v1 * Wout[lane * 2 + 1];
#pragma unroll
    for (int o = 16; o > 0; o >>= 1) p += __shfl_xor_sync(0xffffffffu, p, o);
    if (lane == 0) out[n] = p + bout[0];
}

// ---------------- launch ------------------------------------------------------
extern "C" void kernel_launch(void* const* d_in, const int* in_sizes, int n_in,
                              void* d_out, int out_size) {
    const float* x    = (const float*)d_in[0];
    const void*  ei   = d_in[1];
    const float* W1   = (const float*)d_in[2];
    const float* as1  = (const float*)d_in[3];
    const float* ad1  = (const float*)d_in[4];
    const float* b1   = (const float*)d_in[5];
    const float* W2   = (const float*)d_in[6];
    const float* as2  = (const float*)d_in[7];
    const float* ad2  = (const float*)d_in[8];
    const float* b2   = (const float*)d_in[9];
    const float* Wout = (const float*)d_in[10];
    const float* bout = (const float*)d_in[11];
    float* out = (float*)d_out;

    const int EB = (E2 + 255) / 256;            // edge-parallel blocks
    const int EB16 = (E2 * 16 + 255) / 256;     // half-warp-per-edge blocks

    k_probe<<<1, 256>>>((const int*)ei);
    k_convert<<<EB, 256>>>(ei);

    // layer 1
    k_l1<<<N_NODES / 32, 256>>>(x, W1, as1, ad1);
    k_edge_max<<<EB, 256>>>();
    k_edge_acc<<<EB16, 256>>>();

    // layer 2 (finalize 1 fused in)
    k_l2<<<N_NODES / 32, 256>>>(W2, as2, ad2, b1);
    k_edge_max<<<EB, 256>>>();
    k_edge_acc<<<EB16, 256>>>();

    // output head (finalize 2 fused in)
    k_out<<<N_NODES / 8, 256>>>(b2, Wout, bout, out);
}

// round 4
// speedup vs baseline: 1.5308x; 1.5308x over previous
#include <cuda_runtime.h>
#include <cstdint>

#define N_NODES 100000
#define E_EDGES 1600000
#define E2 (E_EDGES + N_NODES)   // 1,700,000 with self loops
#define HID 64
#define IN_DIM 128
#define NEG_SLOPE 0.2f
#define SCAN_CHUNK 1024
#define NCHUNKS ((N_NODES + SCAN_CHUNK - 1) / SCAN_CHUNK)   // 98

// ---------------- scratch (device globals) ------------------------------------
__device__ float g_h[(size_t)N_NODES * HID];      // transformed features (current layer)
__device__ float g_agg[(size_t)N_NODES * HID];    // normalized aggregate (per layer)
__device__ float g_as[N_NODES], g_ad[N_NODES];    // per-node alpha_src / alpha_dst
__device__ int   g_src[E2], g_dst[E2];            // converted int32 edge list (+loops)
__device__ int   g_csr_src[E2];                   // dst-sorted src indices
__device__ int   g_cnt[N_NODES];                  // per-dst degree histogram
__device__ int   g_cur[N_NODES];                  // scatter cursors
__device__ int   g_base[N_NODES];                 // per-chunk exclusive scan
__device__ int   g_part[128], g_partsc[128];      // chunk partials / scanned
__device__ int   g_rowptr[N_NODES + 1];           // CSR row pointers
__device__ int   g_is64;                          // edge_index dtype flag

// ---------------- helpers -----------------------------------------------------
__device__ __forceinline__ float elu_f(float v) { return v > 0.f ? v : expm1f(v); }

__device__ __forceinline__ int warp_incl_scan(int v) {
    int lane = threadIdx.x & 31;
#pragma unroll
    for (int o = 1; o < 32; o <<= 1) {
        int t = __shfl_up_sync(0xffffffffu, v, o);
        if (lane >= o) v += t;
    }
    return v;
}

// ---------------- dtype probe -------------------------------------------------
__global__ void k_probe(const int* ei32) {
    __shared__ int nz;
    if (threadIdx.x == 0) nz = 0;
    __syncthreads();
    int any = 0;
    for (int i = threadIdx.x; i < 2048; i += 256)
        any |= (ei32[2 * i + 1] != 0);
    if (any) atomicOr(&nz, 1);
    __syncthreads();
    if (threadIdx.x == 0) g_is64 = (nz == 0) ? 1 : 0;
}

// ---------------- zero counters -----------------------------------------------
__global__ void k_zero() {
    int i = blockIdx.x * blockDim.x + threadIdx.x;
    if (i < N_NODES) { g_cnt[i] = 0; g_cur[i] = 0; }
}

// ---------------- convert edge list + histogram by dst ------------------------
__global__ void k_convert(const void* ei) {
    int i = blockIdx.x * blockDim.x + threadIdx.x;
    if (i >= E2) return;
    int s, d;
    if (i < E_EDGES) {
        if (g_is64) {
            const long long* p = (const long long*)ei;
            s = (int)p[i]; d = (int)p[E_EDGES + i];
        } else {
            const int* p = (const int*)ei;
            s = p[i]; d = p[E_EDGES + i];
        }
    } else {
        s = d = i - E_EDGES;
    }
    g_src[i] = s;
    g_dst[i] = d;
    atomicAdd(&g_cnt[d], 1);
}

// ---------------- block scan of histogram (chunk=1024) ------------------------
__global__ __launch_bounds__(SCAN_CHUNK) void k_scan1() {
    __shared__ int wsum[32];
    int b = blockIdx.x;
    int i = b * SCAN_CHUNK + threadIdx.x;
    int lane = threadIdx.x & 31, wid = threadIdx.x >> 5;
    int v = (i < N_NODES) ? g_cnt[i] : 0;
    int inc = warp_incl_scan(v);
    if (lane == 31) wsum[wid] = inc;
    __syncthreads();
    if (wid == 0) wsum[lane] = warp_incl_scan(wsum[lane]);   // full warp participates
    __syncthreads();
    int off = wid ? wsum[wid - 1] : 0;
    if (i < N_NODES) g_base[i] = off + inc - v;   // exclusive within chunk
    if (threadIdx.x == SCAN_CHUNK - 1) g_part[b] = wsum[31];
}

// second level: 128 partials scanned by ONE FULL warp (4 values per lane).
__global__ __launch_bounds__(32) void k_scan2() {
    int lane = threadIdx.x;   // 0..31, one warp
    // each lane owns 4 consecutive partials: serial prefix within lane
    int v0 = g_part[lane * 4 + 0];
    int v1 = g_part[lane * 4 + 1];
    int v2 = g_part[lane * 4 + 2];
    int v3 = g_part[lane * 4 + 3];
    int lsum = v0 + v1 + v2 + v3;
    // inclusive warp scan of lane sums (all 32 lanes participate)
    int inc = lsum;
#pragma unroll
    for (int o = 1; o < 32; o <<= 1) {
        int t = __shfl_up_sync(0xffffffffu, inc, o);
        if (lane >= o) inc += t;
    }
    int excl = inc - lsum;    // exclusive base for this lane's group of 4
    g_partsc[lane * 4 + 0] = excl;
    g_partsc[lane * 4 + 1] = excl + v0;
    g_partsc[lane * 4 + 2] = excl + v0 + v1;
    g_partsc[lane * 4 + 3] = excl + v0 + v1 + v2;
}

__global__ void k_rowptr() {
    int i = blockIdx.x * blockDim.x + threadIdx.x;
    if (i < N_NODES) g_rowptr[i] = g_base[i] + g_partsc[i >> 10];
    if (i == 0) g_rowptr[N_NODES] = E2;
}

// ---------------- scatter edges into CSR order --------------------------------
__global__ void k_scatter() {
    int i = blockIdx.x * blockDim.x + threadIdx.x;
    if (i >= E2) return;
    int d = g_dst[i];
    int pos = g_rowptr[d] + atomicAdd(&g_cur[d], 1);
    g_csr_src[pos] = g_src[i];
}

// ---------------- layer1: h = x @ W1, per-node alphas -------------------------
__global__ __launch_bounds__(256) void k_l1(const float* __restrict__ x,
                                            const float* __restrict__ W1,
                                            const float* __restrict__ as1,
                                            const float* __restrict__ ad1) {
    __shared__ float sW[IN_DIM * HID];   // 32 KB
    __shared__ float sx[32 * IN_DIM];    // 16 KB (reused as sh[32*65])
    int tid = threadIdx.x;
    int node0 = blockIdx.x * 32;
    {
        float4* dw = (float4*)sW; const float4* swg = (const float4*)W1;
        for (int i = tid; i < (IN_DIM * HID) / 4; i += 256) dw[i] = swg[i];
        float4* dx = (float4*)sx;
        const float4* sxg = (const float4*)(x + (size_t)node0 * IN_DIM);
        for (int i = tid; i < (32 * IN_DIM) / 4; i += 256) dx[i] = sxg[i];
    }
    __syncthreads();

    int d = tid & 63, g = tid >> 6;
    float acc[8];
#pragma unroll
    for (int j = 0; j < 8; j++) acc[j] = 0.f;
    for (int k = 0; k < IN_DIM; k += 4) {
        float w0 = sW[(k + 0) * HID + d];
        float w1 = sW[(k + 1) * HID + d];
        float w2 = sW[(k + 2) * HID + d];
        float w3 = sW[(k + 3) * HID + d];
#pragma unroll
        for (int j = 0; j < 8; j++) {
            float4 xv = *(const float4*)&sx[(g * 8 + j) * IN_DIM + k];
            acc[j] = fmaf(w0, xv.x, acc[j]);
            acc[j] = fmaf(w1, xv.y, acc[j]);
            acc[j] = fmaf(w2, xv.z, acc[j]);
            acc[j] = fmaf(w3, xv.w, acc[j]);
        }
    }
    __syncthreads();
    float* sh = sx;
#pragma unroll
    for (int j = 0; j < 8; j++) {
        int n = g * 8 + j;
        sh[n * 65 + d] = acc[j];
        g_h[(size_t)(node0 + n) * HID + d] = acc[j];
    }
    __syncthreads();
    if (tid < 32) {
        int gn = node0 + tid;
        float s = 0.f, dd = 0.f;
#pragma unroll
        for (int k = 0; k < HID; k++) {
            float hv = sh[tid * 65 + k];
            s  = fmaf(hv, as1[k], s);
            dd = fmaf(hv, ad1[k], dd);
        }
        g_as[gn] = s; g_ad[gn] = dd;
    }
}

// ---------------- CSR aggregate: softmax-weighted gather, normalized ----------
// warp per dst node; two 16-lane groups handle two edges per iteration.
__global__ __launch_bounds__(256) void k_agg() {
    int n = blockIdx.x * 8 + (threadIdx.x >> 5);
    if (n >= N_NODES) return;
    int lane = threadIdx.x & 31;
    int grp = lane >> 4, r = lane & 15;
    int beg = g_rowptr[n], end = g_rowptr[n + 1];
    float add = g_ad[n];
    float ax = 0.f, ay = 0.f, az = 0.f, aw = 0.f, dsum = 0.f;
    for (int j = beg + grp; j < end; j += 2) {
        int s = g_csr_src[j];
        float e = g_as[s] + add;
        e = fmaxf(e, NEG_SLOPE * e);
        float ex = __expf(e);
        const float4 hv = *(const float4*)&g_h[(size_t)s * HID + r * 4];
        ax = fmaf(ex, hv.x, ax);
        ay = fmaf(ex, hv.y, ay);
        az = fmaf(ex, hv.z, az);
        aw = fmaf(ex, hv.w, aw);
        dsum += ex;
    }
    ax += __shfl_xor_sync(0xffffffffu, ax, 16);
    ay += __shfl_xor_sync(0xffffffffu, ay, 16);
    az += __shfl_xor_sync(0xffffffffu, az, 16);
    aw += __shfl_xor_sync(0xffffffffu, aw, 16);
    dsum += __shfl_xor_sync(0xffffffffu, dsum, 16);
    float inv = 1.f / dsum;                 // self loop => dsum > 0
    if (grp == 0) {
        float4 o = { ax * inv, ay * inv, az * inv, aw * inv };
        *(float4*)&g_agg[(size_t)n * HID + r * 4] = o;
    }
}

// ---------------- layer2: elu(agg+b1) @ W2, new alphas ------------------------
__global__ __launch_bounds__(256) void k_l2(const float* __restrict__ W2,
                                            const float* __restrict__ as2,
                                            const float* __restrict__ ad2,
                                            const float* __restrict__ b1) {
    __shared__ float sW[HID * HID];   // 16 KB
    __shared__ float sh1[32 * 68];
    __shared__ float sh2[32 * 65];
    int tid = threadIdx.x;
    int node0 = blockIdx.x * 32;
    {
        float4* dw = (float4*)sW; const float4* swg = (const float4*)W2;
        for (int i = tid; i < (HID * HID) / 4; i += 256) dw[i] = swg[i];
    }
    int d = tid & 63, g = tid >> 6;
#pragma unroll
    for (int j = 0; j < 8; j++) {
        int n = g * 8 + j;
        float v = g_agg[(size_t)(node0 + n) * HID + d] + b1[d];
        sh1[n * 68 + d] = elu_f(v);
    }
    __syncthreads();
    float acc[8];
#pragma unroll
    for (int j = 0; j < 8; j++) acc[j] = 0.f;
    for (int k = 0; k < HID; k += 4) {
        float w0 = sW[(k + 0) * HID + d];
        float w1 = sW[(k + 1) * HID + d];
        float w2 = sW[(k + 2) * HID + d];
        float w3 = sW[(k + 3) * HID + d];
#pragma unroll
        for (int j = 0; j < 8; j++) {
            float4 xv = *(const float4*)&sh1[(g * 8 + j) * 68 + k];
            acc[j] = fmaf(w0, xv.x, acc[j]);
            acc[j] = fmaf(w1, xv.y, acc[j]);
            acc[j] = fmaf(w2, xv.z, acc[j]);
            acc[j] = fmaf(w3, xv.w, acc[j]);
        }
    }
#pragma unroll
    for (int j = 0; j < 8; j++) {
        int n = g * 8 + j;
        sh2[n * 65 + d] = acc[j];
        g_h[(size_t)(node0 + n) * HID + d] = acc[j];
    }
    __syncthreads();
    if (tid < 32) {
        int gn = node0 + tid;
        float s = 0.f, dd = 0.f;
#pragma unroll
        for (int k = 0; k < HID; k++) {
            float hv = sh2[tid * 65 + k];
            s  = fmaf(hv, as2[k], s);
            dd = fmaf(hv, ad2[k], dd);
        }
        g_as[gn] = s; g_ad[gn] = dd;
    }
}

// ---------------- output head -------------------------------------------------
__global__ __launch_bounds__(256) void k_out(const float* __restrict__ b2,
                                             const float* __restrict__ Wout,
                                             const float* __restrict__ bout,
                                             float* __restrict__ out) {
    int n = blockIdx.x * 8 + (threadIdx.x >> 5);
    if (n >= N_NODES) return;
    int lane = threadIdx.x & 31;
    float2 a = *(const float2*)&g_agg[(size_t)n * HID + lane * 2];
    float v0 = elu_f(a.x + b2[lane * 2]);
    float v1 = elu_f(a.y + b2[lane * 2 + 1]);
    float p = v0 * Wout[lane * 2] + v1 * Wout[lane * 2 + 1];
#pragma unroll
    for (int o = 16; o > 0; o >>= 1) p += __shfl_xor_sync(0xffffffffu, p, o);
    if (lane == 0) out[n] = p + bout[0];
}

// ---------------- launch ------------------------------------------------------
extern "C" void kernel_launch(void* const* d_in, const int* in_sizes, int n_in,
                              void* d_out, int out_size) {
    const float* x    = (const float*)d_in[0];
    const void*  ei   = d_in[1];
    const float* W1   = (const float*)d_in[2];
    const float* as1  = (const float*)d_in[3];
    const float* ad1  = (const float*)d_in[4];
    const float* b1   = (const float*)d_in[5];
    const float* W2   = (const float*)d_in[6];
    const float* as2  = (const float*)d_in[7];
    const float* ad2  = (const float*)d_in[8];
    const float* b2   = (const float*)d_in[9];
    const float* Wout = (const float*)d_in[10];
    const float* bout = (const float*)d_in[11];
    float* out = (float*)d_out;

    const int EB = (E2 + 255) / 256;

    // CSR build (shared by both layers)
    k_probe<<<1, 256>>>((const int*)ei);
    k_zero<<<(N_NODES + 255) / 256, 256>>>();
    k_convert<<<EB, 256>>>(ei);
    k_scan1<<<NCHUNKS, SCAN_CHUNK>>>();
    k_scan2<<<1, 32>>>();
    k_rowptr<<<(N_NODES + 255) / 256, 256>>>();
    k_scatter<<<EB, 256>>>();

    // layer 1
    k_l1<<<N_NODES / 32, 256>>>(x, W1, as1, ad1);
    k_agg<<<(N_NODES + 7) / 8, 256>>>();

    // layer 2
    k_l2<<<N_NODES / 32, 256>>>(W2, as2, ad2, b1);
    k_agg<<<(N_NODES + 7) / 8, 256>>>();

    // output head
    k_out<<<(N_NODES + 7) / 8, 256>>>(b2, Wout, bout, out);
}